// round 2
// baseline (speedup 1.0000x reference)
#include <cuda_runtime.h>
#include <math.h>

#define BATCH 2
#define SEQ   2048
#define EMB   1024
#define HEADS 16
#define HD    64
#define MROWS (BATCH*SEQ)   // 4096

// Scratch (allocation-free rule: __device__ globals)
__device__ float g_q[(size_t)MROWS * EMB];
__device__ float g_k[(size_t)MROWS * EMB];
__device__ float g_v[(size_t)MROWS * EMB];
__device__ float g_attn[(size_t)MROWS * EMB];

// ---------------------------------------------------------------------------
// C = A[M,K] @ W[N,K]^T + bias[N]
// SPLIT=true: N=3072, de-interleave columns into Cq/Ck/Cv each [M,1024]
// SPLIT=false: write C0 [M,N]
// BM=BN=128, BK=16, 256 threads, 8x8 per thread.
// ---------------------------------------------------------------------------
template <bool SPLIT>
__global__ void __launch_bounds__(256)
sgemm_bias_kernel(const float* __restrict__ A, const float* __restrict__ W,
                  const float* __restrict__ bias,
                  float* __restrict__ C0, float* __restrict__ C1, float* __restrict__ C2,
                  int M, int N, int K)
{
    const int BM = 128, BN = 128, BK = 16;
    __shared__ float As[BK][BM + 4];
    __shared__ float Ws[BK][BN + 4];

    const int bm = blockIdx.y * BM;
    const int bn = blockIdx.x * BN;
    const int tid = threadIdx.x;
    const int tx = tid & 15;        // 0..15 -> n
    const int ty = tid >> 4;        // 0..15 -> m

    float acc[8][8];
#pragma unroll
    for (int i = 0; i < 8; i++)
#pragma unroll
        for (int j = 0; j < 8; j++) acc[i][j] = 0.f;

    const float* Ag = A + (size_t)bm * K;
    const float* Wg = W + (size_t)bn * K;

    for (int kt = 0; kt < K; kt += BK) {
#pragma unroll
        for (int r = 0; r < 2; r++) {
            int idx = tid + r * 256;          // 0..511 float4 slots
            int row = idx >> 2;               // 0..127
            int kq  = (idx & 3) << 2;         // 0,4,8,12
            float4 av = *(const float4*)(Ag + (size_t)row * K + kt + kq);
            As[kq + 0][row] = av.x; As[kq + 1][row] = av.y;
            As[kq + 2][row] = av.z; As[kq + 3][row] = av.w;
            float4 wv = *(const float4*)(Wg + (size_t)row * K + kt + kq);
            Ws[kq + 0][row] = wv.x; Ws[kq + 1][row] = wv.y;
            Ws[kq + 2][row] = wv.z; Ws[kq + 3][row] = wv.w;
        }
        __syncthreads();

#pragma unroll
        for (int kk = 0; kk < BK; kk++) {
            float a[8], b[8];
#pragma unroll
            for (int i = 0; i < 8; i++) a[i] = As[kk][ty * 8 + i];
#pragma unroll
            for (int j = 0; j < 8; j++) b[j] = Ws[kk][tx * 8 + j];
#pragma unroll
            for (int i = 0; i < 8; i++)
#pragma unroll
                for (int j = 0; j < 8; j++) acc[i][j] += a[i] * b[j];
        }
        __syncthreads();
    }

    // Bias (per-thread columns)
    float bj[8];
#pragma unroll
    for (int j = 0; j < 8; j++) bj[j] = bias[bn + tx * 8 + j];

    // Destination: a 128-wide tile never crosses a 1024 column boundary
    float* dst;
    int nbase, ldd;
    if (SPLIT) {
        int which = bn >> 10;
        dst = (which == 0) ? C0 : (which == 1) ? C1 : C2;
        nbase = (bn & 1023) + tx * 8;
        ldd = EMB;
    } else {
        dst = C0;
        nbase = bn + tx * 8;
        ldd = N;
    }

#pragma unroll
    for (int i = 0; i < 8; i++) {
        int m = bm + ty * 8 + i;
        float4* drow = (float4*)(dst + (size_t)m * ldd + nbase);
#pragma unroll
        for (int jj = 0; jj < 2; jj++) {
            float4 v;
            v.x = acc[i][jj * 4 + 0] + bj[jj * 4 + 0];
            v.y = acc[i][jj * 4 + 1] + bj[jj * 4 + 1];
            v.z = acc[i][jj * 4 + 2] + bj[jj * 4 + 2];
            v.w = acc[i][jj * 4 + 3] + bj[jj * 4 + 3];
            drow[jj] = v;
        }
    }
}

// ---------------------------------------------------------------------------
// Causal flash attention, fp32, D=64.
// Q/K/V layout: [B,H,S,D] contiguous (the no-transpose reshape makes head h of
// batch b a contiguous [S,D] slab). Output written transposed to [B,S,E] with
// column offset h*D.
// 128 queries per CTA (one per thread), K/V in 64x64 smem tiles.
// ---------------------------------------------------------------------------
__global__ void __launch_bounds__(128)
attn_kernel(const float* __restrict__ gq, const float* __restrict__ gk,
            const float* __restrict__ gv, float* __restrict__ gout)
{
    __shared__ float ks[64][HD];   // 16 KB
    __shared__ float vs[64][HD];   // 16 KB

    const int tid = threadIdx.x;
    const int b = blockIdx.z, h = blockIdx.y;
    const int q0 = blockIdx.x * 128;
    const int sq = q0 + tid;

    const float* Qp    = gq + ((size_t)(b * HEADS + h) * SEQ + sq) * HD;
    const float* Kbase = gk + (size_t)(b * HEADS + h) * SEQ * HD;
    const float* Vbase = gv + (size_t)(b * HEADS + h) * SEQ * HD;

    float q[HD];
#pragma unroll
    for (int i = 0; i < HD / 4; i++) {
        float4 t = ((const float4*)Qp)[i];
        q[4 * i + 0] = t.x; q[4 * i + 1] = t.y;
        q[4 * i + 2] = t.z; q[4 * i + 3] = t.w;
    }

    float o[HD];
#pragma unroll
    for (int d = 0; d < HD; d++) o[d] = 0.f;
    float m = -INFINITY, l = 0.f;

    const int kend = q0 + 128;   // exclusive causal limit for this CTA
    for (int kt = 0; kt < kend; kt += 64) {
        __syncthreads();
#pragma unroll
        for (int r = 0; r < 8; r++) {
            int idx = tid + r * 128;          // 0..1023 float4 slots
            int row = idx >> 4;               // 0..63
            int c   = (idx & 15) << 2;
            *(float4*)&ks[row][c] = *(const float4*)(Kbase + (size_t)(kt + row) * HD + c);
            *(float4*)&vs[row][c] = *(const float4*)(Vbase + (size_t)(kt + row) * HD + c);
        }
        __syncthreads();

        int jmax = min(64, sq + 1 - kt);
        for (int j = 0; j < jmax; j++) {
            const float4* kr = (const float4*)ks[j];
            float s0 = 0.f, s1 = 0.f, s2 = 0.f, s3 = 0.f;
#pragma unroll
            for (int d4 = 0; d4 < HD / 4; d4++) {
                float4 kv = kr[d4];
                s0 += q[4 * d4 + 0] * kv.x;
                s1 += q[4 * d4 + 1] * kv.y;
                s2 += q[4 * d4 + 2] * kv.z;
                s3 += q[4 * d4 + 3] * kv.w;
            }
            float s = ((s0 + s1) + (s2 + s3)) * 0.125f;   // 1/sqrt(64)

            const float4* vr = (const float4*)vs[j];
            if (s > m) {
                float corr = __expf(m - s);   // exp(-inf)=0 on first key
                m = s;
                l = l * corr + 1.f;
#pragma unroll
                for (int d4 = 0; d4 < HD / 4; d4++) {
                    float4 vv = vr[d4];
                    o[4 * d4 + 0] = o[4 * d4 + 0] * corr + vv.x;
                    o[4 * d4 + 1] = o[4 * d4 + 1] * corr + vv.y;
                    o[4 * d4 + 2] = o[4 * d4 + 2] * corr + vv.z;
                    o[4 * d4 + 3] = o[4 * d4 + 3] * corr + vv.w;
                }
            } else {
                float p = __expf(s - m);
                l += p;
#pragma unroll
                for (int d4 = 0; d4 < HD / 4; d4++) {
                    float4 vv = vr[d4];
                    o[4 * d4 + 0] += p * vv.x;
                    o[4 * d4 + 1] += p * vv.y;
                    o[4 * d4 + 2] += p * vv.z;
                    o[4 * d4 + 3] += p * vv.w;
                }
            }
        }
    }

    float inv = 1.f / l;
    float* Op = gout + ((size_t)(b * SEQ) + sq) * EMB + h * HD;
#pragma unroll
    for (int i = 0; i < HD / 4; i++) {
        float4 t;
        t.x = o[4 * i + 0] * inv; t.y = o[4 * i + 1] * inv;
        t.z = o[4 * i + 2] * inv; t.w = o[4 * i + 3] * inv;
        ((float4*)Op)[i] = t;
    }
}

// ---------------------------------------------------------------------------

extern "C" void kernel_launch(void* const* d_in, const int* in_sizes, int n_in,
                              void* d_out, int out_size)
{
    const float* x    = (const float*)d_in[0];   // [B,S,E]
    const float* Wqkv = (const float*)d_in[1];   // [3E,E]
    const float* bqkv = (const float*)d_in[2];   // [3E]
    const float* Wout = (const float*)d_in[3];   // [E,E]
    const float* bout = (const float*)d_in[4];   // [E]
    float* out = (float*)d_out;                  // [B,S,E]

    float *gq, *gk, *gv, *ga;
    cudaGetSymbolAddress((void**)&gq, g_q);
    cudaGetSymbolAddress((void**)&gk, g_k);
    cudaGetSymbolAddress((void**)&gv, g_v);
    cudaGetSymbolAddress((void**)&ga, g_attn);

    // 1) QKV projection, de-interleaved into q/k/v
    {
        dim3 grid(3 * EMB / 128, MROWS / 128);   // 24 x 32
        sgemm_bias_kernel<true><<<grid, 256>>>(x, Wqkv, bqkv, gq, gk, gv,
                                               MROWS, 3 * EMB, EMB);
    }
    // 2) Causal attention
    {
        dim3 grid(SEQ / 128, HEADS, BATCH);      // 16 x 16 x 2
        attn_kernel<<<grid, 128>>>(gq, gk, gv, ga);
    }
    // 3) Output projection
    {
        dim3 grid(EMB / 128, MROWS / 128);       // 8 x 32
        sgemm_bias_kernel<false><<<grid, 256>>>(ga, Wout, bout, out,
                                                nullptr, nullptr,
                                                MROWS, EMB, EMB);
    }
}